// round 16
// baseline (speedup 1.0000x reference)
#include <cuda_runtime.h>
#include <cuda_bf16.h>
#include <cuda_fp16.h>
#include <cstdint>
#include <math.h>

#define BQ   32
#define TT   128
#define EE   256
#define HH   512
#define ENCC 512
#define VV   10000
#define G4   2048          // 4*H
#define XW   1280          // E + H + ENC
#define VPAD 10112         // 79 * 128

// ------------------------------------------------------------------
// scratch (static device globals; no allocations allowed)
// ------------------------------------------------------------------
__device__ float g_c0[BQ * HH];
__device__ float g_baseA[BQ * G4];                // K half 0 (+ biases)
__device__ float g_baseB[BQ * G4];                // K half 1
__device__ unsigned g_bar_cnt1[16 * 32];          // level-1 counters, 128B apart
__device__ unsigned g_bar_count;                  // level-2 counter
__device__ unsigned g_bar_gen;

// fp16 operands
__device__ __half g_G16[TT * BQ * G4];            // per-step gate input (16 MB)
__device__ __half g_h16[(TT + 1) * BQ * HH];      // slot0=h0, slot t+1 = h after step t
__device__ __half g_Bh[VPAD * HH];                // logits B (Wv) fp16
__device__ __half g_E[TT * BQ * EE];              // gathered prev-token embeddings
__device__ __half g_Wih16[G4 * EE];               // W_ih[:, :E] fp16
__device__ __half g_Wihb[G4 * 1024];              // W_ih[:, E:] fp16
__device__ __half g_Whh16[G4 * HH];               // W_hh fp16
__device__ __half g_X16[128 * 1024];              // [o|tv] fp16, rows 32..127 zero
__device__ __half g_tv16[128 * HH];               // tv fp16, rows 32..127 zero
__device__ __half g_W3h[3 * HH * HH];             // [Wo;Wh;Wc] fp16

// ------------------------------------------------------------------
// merged conversion + gather kernel. chunk = 4 fp32 / 8 fp16 elems.
// cum ranges: 4096 8192 204800 335872 860160 1122304 2416640 2678784
// grid = 10464 x 256
// ------------------------------------------------------------------
__global__ void k_convAll(const float* __restrict__ tv,
                          const float* __restrict__ Wo,
                          const float* __restrict__ Wh,
                          const float* __restrict__ Wc,
                          const float* __restrict__ W_ih,
                          const float* __restrict__ W_hh,
                          const float* __restrict__ Wv,
                          const float* __restrict__ emb,
                          const int*   __restrict__ texts,
                          const int*   __restrict__ startp)
{
    int ci = blockIdx.x * 256 + threadIdx.x;
    if (ci < 4096) {
        int e = ci * 4;                              // 32*512 tv -> g_tv16
        float4 v = *(const float4*)(tv + e);
        *(__half2*)(g_tv16 + e)     = __floats2half2_rn(v.x, v.y);
        *(__half2*)(g_tv16 + e + 2) = __floats2half2_rn(v.z, v.w);
    } else if (ci < 8192) {
        int e = (ci - 4096) * 4;                     // tv -> X16 cols 512..1023
        int b = e >> 9, k = e & 511;
        float4 v = *(const float4*)(tv + b * ENCC + k);
        *(__half2*)(g_X16 + b * 1024 + 512 + k)     = __floats2half2_rn(v.x, v.y);
        *(__half2*)(g_X16 + b * 1024 + 512 + k + 2) = __floats2half2_rn(v.z, v.w);
    } else if (ci < 204800) {
        int e = (ci - 8192) * 4;
        int n = e >> 9, k = e & 511;
        const float* src = (n < 512) ? (Wo + n * 512 + k)
                         : (n < 1024) ? (Wh + (n - 512) * 512 + k)
                                      : (Wc + (n - 1024) * 512 + k);
        float4 v = *(const float4*)src;
        *(__half2*)(g_W3h + e)     = __floats2half2_rn(v.x, v.y);
        *(__half2*)(g_W3h + e + 2) = __floats2half2_rn(v.z, v.w);
    } else if (ci < 335872) {
        int e = (ci - 204800) * 4;
        int n = e >> 8, k = e & 255;
        float4 v = *(const float4*)(W_ih + (size_t)n * XW + k);
        *(__half2*)(g_Wih16 + (size_t)n * EE + k)     = __floats2half2_rn(v.x, v.y);
        *(__half2*)(g_Wih16 + (size_t)n * EE + k + 2) = __floats2half2_rn(v.z, v.w);
    } else if (ci < 860160) {
        int e = (ci - 335872) * 4;
        int n = e >> 10, k = e & 1023;
        float4 v = *(const float4*)(W_ih + (size_t)n * XW + EE + k);
        *(__half2*)(g_Wihb + (size_t)n * 1024 + k)     = __floats2half2_rn(v.x, v.y);
        *(__half2*)(g_Wihb + (size_t)n * 1024 + k + 2) = __floats2half2_rn(v.z, v.w);
    } else if (ci < 1122304) {
        int e = (ci - 860160) * 4;
        float4 v = *(const float4*)(W_hh + e);
        *(__half2*)(g_Whh16 + e)     = __floats2half2_rn(v.x, v.y);
        *(__half2*)(g_Whh16 + e + 2) = __floats2half2_rn(v.z, v.w);
    } else if (ci < 2416640) {
        size_t e = (size_t)(ci - 1122304) * 4;
        int n = (int)(e >> 9);
        if (n < VV) {
            float4 v = *(const float4*)(Wv + e);
            *(__half2*)(g_Bh + e)     = __floats2half2_rn(v.x, v.y);
            *(__half2*)(g_Bh + e + 2) = __floats2half2_rn(v.z, v.w);
        } else {
            *(__half2*)(g_Bh + e)     = __floats2half2_rn(0.f, 0.f);
            *(__half2*)(g_Bh + e + 2) = __floats2half2_rn(0.f, 0.f);
        }
    } else if (ci < 2678784) {
        int idx = ci - 2416640;                      // gather: 4096 rows x 64 chunks
        int r = idx >> 6, k = (idx & 63) * 4;
        int t = r >> 5, b = r & 31;
        int tok = (t == 0) ? startp[0] : texts[b * TT + t - 1];
        float4 v = *(const float4*)(emb + (size_t)tok * EE + k);
        *(__half2*)(g_E + (size_t)r * EE + k)     = __floats2half2_rn(v.x, v.y);
        *(__half2*)(g_E + (size_t)r * EE + k + 2) = __floats2half2_rn(v.z, v.w);
    }
}

// ------------------------------------------------------------------
// mma / ldmatrix / cp.async helpers
// ------------------------------------------------------------------
__device__ __forceinline__ void cp_async16(uint32_t dst, const void* src)
{
    asm volatile("cp.async.cg.shared.global [%0], [%1], 16;" :: "r"(dst), "l"(src));
}
__device__ __forceinline__ void cp_async8(uint32_t dst, const void* src)
{
    asm volatile("cp.async.ca.shared.global [%0], [%1], 8;" :: "r"(dst), "l"(src));
}
__device__ __forceinline__ void cp_commit()
{
    asm volatile("cp.async.commit_group;");
}
__device__ __forceinline__ void cp_wait_all()
{
    asm volatile("cp.async.wait_group 0;");
}
__device__ __forceinline__ void ldsm_x4(uint32_t& r0, uint32_t& r1,
                                        uint32_t& r2, uint32_t& r3, uint32_t addr)
{
    asm volatile("ldmatrix.sync.aligned.m8n8.x4.shared.b16 {%0,%1,%2,%3}, [%4];"
                 : "=r"(r0), "=r"(r1), "=r"(r2), "=r"(r3) : "r"(addr));
}
__device__ __forceinline__ void ldsm_x2(uint32_t& r0, uint32_t& r1, uint32_t addr)
{
    asm volatile("ldmatrix.sync.aligned.m8n8.x2.shared.b16 {%0,%1}, [%2];"
                 : "=r"(r0), "=r"(r1) : "r"(addr));
}
__device__ __forceinline__ void mma16816(float& c0, float& c1, float& c2, float& c3,
                                         uint32_t a0, uint32_t a1, uint32_t a2, uint32_t a3,
                                         uint32_t b0, uint32_t b1)
{
    asm volatile("mma.sync.aligned.m16n8k16.row.col.f32.f16.f16.f32 "
                 "{%0,%1,%2,%3}, {%4,%5,%6,%7}, {%8,%9}, {%0,%1,%2,%3};"
                 : "+f"(c0), "+f"(c1), "+f"(c2), "+f"(c3)
                 : "r"(a0), "r"(a1), "r"(a2), "r"(a3), "r"(b0), "r"(b1));
}

__device__ __forceinline__ float fsigm(float x)
{
    x = fminf(fmaxf(x, -30.f), 30.f);
    return __fdividef(1.f, 1.f + __expf(-x));
}
__device__ __forceinline__ float ftanh(float x)
{
    x = fminf(fmaxf(x, -15.f), 15.f);
    float e = __expf(2.f * x);
    return __fdividef(e - 1.f, e + 1.f);
}

// ------------------------------------------------------------------
// kernel: sequential LSTM via HMMA (persistent, 128 CTAs x 128 thr)
// R15 structure + hierarchical (16x8 -> 16) arrival tree barrier.
// SMEM: sW 16x1040 (16640) | sH 32x1040 (33280) | sG 2x1024
// ------------------------------------------------------------------
#define SW_OFF 0
#define SH_OFF 16640
#define SG_OFF 49920
#define LSTM_SMEM 51968

__global__ void __launch_bounds__(128, 1) k_lstm()
{
    extern __shared__ __align__(16) char smem[];
    uint32_t sbase = (uint32_t)__cvta_generic_to_shared(smem);
    __shared__ unsigned sGen;

    const int tid  = threadIdx.x;
    const int lane = tid & 31;
    const int w    = tid >> 5;          // warp 0..3
    const int p    = blockIdx.x;        // 0..127

    for (int i = 0; i < 8; i++) {
        int idx = tid + i * 128;
        int lr = idx >> 6, seg = idx & 63;
        int n  = (lr >> 2) * HH + p * 4 + (lr & 3);
        cp_async16(sbase + SW_OFF + lr * 1040 + seg * 16,
                   g_Whh16 + (size_t)n * HH + seg * 8);
    }
    cp_commit(); cp_wait_all();

    const int q    = lane >> 2;                 // valid for lane<16
    const int colb = w * 8 + (lane & 3) * 2;
    float cs0 = 0.f, cs1 = 0.f;
    if (lane < 16) {
        cs0 = g_c0[colb * HH + p * 4 + q];
        cs1 = g_c0[(colb + 1) * HH + p * 4 + q];
    }

    if (tid == 0) sGen = g_bar_gen;
    __syncthreads();
    const unsigned base_gen = sGen;

    const int amat = lane >> 3;
    const uint32_t aoff = sbase + SW_OFF
        + (uint32_t)(((amat & 1) * 8 + (lane & 7)) * 1040 + ((amat >> 1) * 8) * 2);
    const uint32_t boff = sbase + SH_OFF
        + (uint32_t)((w * 8 + (lane & 7)) * 1040 + (lane >> 3) * 16);

    const int gb_b = tid & 31, gb_g = tid >> 5;

    cp_async8(sbase + SG_OFF + (gb_g * 32 + gb_b) * 8,
              g_G16 + (size_t)gb_b * G4 + gb_g * HH + p * 4);
    cp_commit();

    for (int t = 0; t < TT; t++) {
        {
            const __half* hsrc = g_h16 + (size_t)t * (BQ * HH);
            #pragma unroll
            for (int j = 0; j < 16; j++) {
                int idx = lane + j * 32;
                int row = idx >> 6, seg = idx & 63;
                cp_async16(sbase + SH_OFF + (w * 8 + row) * 1040 + seg * 16,
                           hsrc + (size_t)(w * 8 + row) * HH + seg * 8);
            }
            cp_commit();
        }
        if (t + 1 < TT) {
            cp_async8(sbase + SG_OFF + ((t + 1) & 1) * 1024 + (gb_g * 32 + gb_b) * 8,
                      g_G16 + (size_t)((t + 1) * BQ + gb_b) * G4 + gb_g * HH + p * 4);
            cp_commit();
            asm volatile("cp.async.wait_group 1;");
        } else {
            asm volatile("cp.async.wait_group 0;");
        }
        __syncwarp();

        float acc[4][4];
        #pragma unroll
        for (int s = 0; s < 4; s++)
            { acc[s][0] = 0.f; acc[s][1] = 0.f; acc[s][2] = 0.f; acc[s][3] = 0.f; }

        #pragma unroll
        for (int i = 0; i < 16; i++) {
            uint32_t b0, b1, b2, b3;
            ldsm_x4(b0, b1, b2, b3, boff + i * 64);
            uint32_t a0, a1, a2, a3;
            ldsm_x4(a0, a1, a2, a3, aoff + (2 * i) * 32);
            int s0 = (2 * i) & 3;
            mma16816(acc[s0][0], acc[s0][1], acc[s0][2], acc[s0][3],
                     a0, a1, a2, a3, b0, b1);
            ldsm_x4(a0, a1, a2, a3, aoff + (2 * i + 1) * 32);
            int s1 = (2 * i + 1) & 3;
            mma16816(acc[s1][0], acc[s1][1], acc[s1][2], acc[s1][3],
                     a0, a1, a2, a3, b2, b3);
        }
        float g0 = (acc[0][0] + acc[1][0]) + (acc[2][0] + acc[3][0]);
        float g1 = (acc[0][1] + acc[1][1]) + (acc[2][1] + acc[3][1]);
        float g2 = (acc[0][2] + acc[1][2]) + (acc[2][2] + acc[3][2]);
        float g3 = (acc[0][3] + acc[1][3]) + (acc[2][3] + acc[3][3]);

        __syncthreads();

        const __half* sGc = (const __half*)(smem + SG_OFF + (t & 1) * 1024);
        {
            int r0 = lane >> 2;
            int gg = r0 >> 2, qq = r0 & 3;
            g0 += __half2float(sGc[(gg * 32 + colb) * 4 + qq]);
            g1 += __half2float(sGc[(gg * 32 + colb + 1) * 4 + qq]);
            g2 += __half2float(sGc[((gg + 2) * 32 + colb) * 4 + qq]);
            g3 += __half2float(sGc[((gg + 2) * 32 + colb + 1) * 4 + qq]);
        }

        float f0 = __shfl_xor_sync(0xffffffffu, g0, 16);
        float f1 = __shfl_xor_sync(0xffffffffu, g1, 16);
        float o0 = __shfl_xor_sync(0xffffffffu, g2, 16);
        float o1 = __shfl_xor_sync(0xffffffffu, g3, 16);

        if (lane < 16) {
            float i0 = fsigm(g0), i1 = fsigm(g1);
            float t0 = ftanh(g2), t1 = ftanh(g3);
            float F0 = fsigm(f0), F1 = fsigm(f1);
            float O0 = fsigm(o0), O1 = fsigm(o1);
            cs0 = F0 * cs0 + i0 * t0;
            cs1 = F1 * cs1 + i1 * t1;
            float h0 = O0 * ftanh(cs0);
            float h1 = O1 * ftanh(cs1);
            size_t hb = (size_t)(t + 1) * (BQ * HH) + p * 4 + q;
            g_h16[hb + (size_t)colb * HH]       = __float2half_rn(h0);
            g_h16[hb + (size_t)(colb + 1) * HH] = __float2half_rn(h1);
        }

        // ---- hierarchical grid barrier: 16 groups of 8 -> root of 16 ----
        __threadfence();
        __syncthreads();
        if (tid == 0) {
            unsigned target = base_gen + (unsigned)(t + 1);
            unsigned* cnt1 = &g_bar_cnt1[(p >> 3) * 32];
            unsigned arr1 = atomicAdd(cnt1, 1u);
            if (arr1 == 7u) {
                *cnt1 = 0u;                         // safe: members wait on gen
                unsigned arr2 = atomicAdd(&g_bar_count, 1u);
                if (arr2 == 15u) {
                    g_bar_count = 0u;
                    __threadfence();
                    atomicExch(&g_bar_gen, target);
                } else {
                    volatile unsigned* vg = &g_bar_gen;
                    while (*vg < target) { }
                }
            } else {
                volatile unsigned* vg = &g_bar_gen;
                while (*vg < target) { }
            }
            __threadfence();
        }
        __syncthreads();
    }
}

#define MMA_SMEM_BUF 20480           // A(10240) + B(10240) per buffer

// ------------------------------------------------------------------
// kernel: G = E @ Wih^T + baseA + baseB  (fp16 HMMA, K=256) -> g_G16
// ------------------------------------------------------------------
__device__ __forceinline__ void g_load_tile(
    int kt, int buf, int tid, int mtb, int ntb, uint32_t sbase)
{
    const int k0 = kt * 32;
    const uint32_t abase = sbase + buf * MMA_SMEM_BUF;
    const uint32_t bbase = abase + 10240;
    #pragma unroll
    for (int i = 0; i < 2; i++) {
        int ch  = tid + i * 256;
        int row = ch >> 2, kc = ch & 3;
        cp_async16(abase + row * 80 + kc * 16,
                   g_E + (size_t)(mtb * 128 + row) * EE + k0 + kc * 8);
        cp_async16(bbase + row * 80 + kc * 16,
                   g_Wih16 + (size_t)(ntb * 128 + row) * EE + k0 + kc * 8);
    }
    cp_commit();
}

__global__ void __launch_bounds__(256) k_G_mma()
{
    __shared__ __align__(16) unsigned char smem[2 * MMA_SMEM_BUF];
    const int tid  = threadIdx.x;
    const int lane = tid & 31;
    const int warp = tid >> 5;
    const int ntb  = blockIdx.x;     // 0..15
    const int mtb  = blockIdx.y;     // 0..31

    const int wm = (warp >> 2) * 64;
    const int wn = (warp & 3) * 32;

    uint32_t sbase = (uint32_t)__cvta_generic_to_shared(smem);

    float acc[4][4][4];
    #pragma unroll
    for (int i = 0; i < 4; i++)
        #pragma unroll
        for (int jj = 0; jj < 4; jj++) {
            acc[i][jj][0] = 0.f; acc[i][jj][1] = 0.f;
            acc[i][jj][2] = 0.f; acc[i][jj][3] = 0.f;
        }

    const int amat  = lane >> 3;
    const uint32_t a_lane_off = (uint32_t)((wm + (amat & 1) * 8 + (lane & 7)) * 80
                                           + ((amat >> 1) * 8) * 2);
    const int blane = lane & 15;
    const uint32_t b_lane_off = (uint32_t)(10240 + (wn + (blane & 7)) * 80
                                           + ((blane >> 3) * 8) * 2);

    const int NKT = 8;
    g_load_tile(0, 0, tid, mtb, ntb, sbase);

    for (int kt = 0; kt < NKT; kt++) {
        if (kt + 1 < NKT) {
            g_load_tile(kt + 1, (kt + 1) & 1, tid, mtb, ntb, sbase);
            asm volatile("cp.async.wait_group 1;");
        } else {
            asm volatile("cp.async.wait_group 0;");
        }
        __syncthreads();

        const uint32_t abase = sbase + (kt & 1) * MMA_SMEM_BUF;
        #pragma unroll
        for (int k16 = 0; k16 < 2; k16++) {
            uint32_t af[4][4];
            uint32_t bf[4][2];
            #pragma unroll
            for (int mt = 0; mt < 4; mt++) {
                uint32_t ad = abase + a_lane_off + mt * (16 * 80) + k16 * 32;
                ldsm_x4(af[mt][0], af[mt][1], af[mt][2], af[mt][3], ad);
            }
            #pragma unroll
            for (int nt = 0; nt < 4; nt++) {
                uint32_t bd = abase + b_lane_off + nt * (8 * 80) + k16 * 32;
                ldsm_x2(bf[nt][0], bf[nt][1], bd);
            }
            #pragma unroll
            for (int mt = 0; mt < 4; mt++)
                #pragma unroll
                for (int nt = 0; nt < 4; nt++)
                    mma16816(acc[mt][nt][0], acc[mt][nt][1],
                             acc[mt][nt][2], acc[mt][nt][3],
                             af[mt][0], af[mt][1], af[mt][2], af[mt][3],
                             bf[nt][0], bf[nt][1]);
        }
        __syncthreads();
    }

    #pragma unroll
    for (int mt = 0; mt < 4; mt++) {
        #pragma unroll
        for (int nt = 0; nt < 4; nt++) {
            int col = ntb * 128 + wn + nt * 8 + (lane & 3) * 2;
            int m0 = mtb * 128 + wm + mt * 16 + (lane >> 2);
            float2 ba0 = *(const float2*)&g_baseA[(m0 & 31) * G4 + col];
            float2 bb0 = *(const float2*)&g_baseB[(m0 & 31) * G4 + col];
            *(__half2*)&g_G16[(size_t)m0 * G4 + col] =
                __floats2half2_rn(acc[mt][nt][0] + ba0.x + bb0.x,
                                  acc[mt][nt][1] + ba0.y + bb0.y);
            int m1 = m0 + 8;
            float2 ba1 = *(const float2*)&g_baseA[(m1 & 31) * G4 + col];
            float2 bb1 = *(const float2*)&g_baseB[(m1 & 31) * G4 + col];
            *(__half2*)&g_G16[(size_t)m1 * G4 + col] =
                __floats2half2_rn(acc[mt][nt][2] + ba1.x + bb1.x,
                                  acc[mt][nt][3] + ba1.y + bb1.y);
        }
    }
}

// ------------------------------------------------------------------
// kernel: base = X @ Wihb^T + biases, split-K x2 (fp16 HMMA, K=512 each)
// ------------------------------------------------------------------
__device__ __forceinline__ void base_load_tile(
    int kt, int buf, int tid, int ntb, int kbase, uint32_t sbase)
{
    const int k0 = kbase + kt * 32;
    const uint32_t abase = sbase + buf * MMA_SMEM_BUF;
    const uint32_t bbase = abase + 10240;
    #pragma unroll
    for (int i = 0; i < 2; i++) {
        int ch  = tid + i * 256;
        int row = ch >> 2, kc = ch & 3;
        cp_async16(abase + row * 80 + kc * 16,
                   g_X16 + (size_t)row * 1024 + k0 + kc * 8);
        cp_async16(bbase + row * 80 + kc * 16,
                   g_Wihb + (size_t)(ntb * 128 + row) * 1024 + k0 + kc * 8);
    }
    cp_commit();
}

__global__ void __launch_bounds__(256) k_base_mma(const float* __restrict__ b_ih,
                                                  const float* __restrict__ b_hh)
{
    __shared__ __align__(16) unsigned char smem[2 * MMA_SMEM_BUF];
    const int tid  = threadIdx.x;
    const int lane = tid & 31;
    const int warp = tid >> 5;
    const int ntb  = blockIdx.x & 15;
    const int kh   = blockIdx.x >> 4;      // 0 or 1
    const int kbase = kh * 512;

    const int wm = (warp >> 2) * 64;
    const int wn = (warp & 3) * 32;

    uint32_t sbase = (uint32_t)__cvta_generic_to_shared(smem);

    float acc[4][4][4];
    #pragma unroll
    for (int i = 0; i < 4; i++)
        #pragma unroll
        for (int jj = 0; jj < 4; jj++) {
            acc[i][jj][0] = 0.f; acc[i][jj][1] = 0.f;
            acc[i][jj][2] = 0.f; acc[i][jj][3] = 0.f;
        }

    const int amat  = lane >> 3;
    const uint32_t a_lane_off = (uint32_t)((wm + (amat & 1) * 8 + (lane & 7)) * 80
                                           + ((amat >> 1) * 8) * 2);
    const int blane = lane & 15;
    const uint32_t b_lane_off = (uint32_t)(10240 + (wn + (blane & 7)) * 80
                                           + ((blane >> 3) * 8) * 2);

    const int NKT = 16;                    // 512 / 32
    base_load_tile(0, 0, tid, ntb, kbase, sbase);

    for (int kt = 0; kt < NKT; kt++) {
        if (kt + 1 < NKT) {
            base_load_tile(kt + 1, (kt + 1) & 1, tid, ntb, kbase, sbase);
            asm volatile("cp.async.wait_group 1;");
        } else {
            asm volatile("cp.async.wait_group 0;");
        }
        __syncthreads();

        const uint32_t abase = sbase + (kt & 1) * MMA_SMEM_BUF;
        #pragma unroll
        for (int k16 = 0; k16 < 2; k16++) {
            uint32_t af[4][4];
            uint32_t bf[4][2];
            #pragma unroll
            for (int mt = 0; mt < 4; mt++) {
                uint32_t ad = abase + a_lane_off + mt * (16 * 80) + k16 * 32;
                ldsm_x4(af[mt][0], af[mt][1], af[mt][2], af[mt][3], ad);
            }
            #pragma unroll
            for (int nt = 0; nt < 4; nt++) {
                uint32_t bd = abase + b_lane_off + nt * (8 * 80) + k16 * 32;
                ldsm_x2(bf[nt][0], bf[nt][1], bd);
            }
            #pragma unroll
            for (int mt = 0; mt < 4; mt++)
                #pragma unroll
                for (int nt = 0; nt < 4; nt++)
                    mma16816(acc[mt][nt][0], acc[mt][nt][1],
                             acc[mt][nt][2], acc[mt][nt][3],
                             af[mt][0], af[mt][1], af[mt][2], af[mt][3],
                             bf[nt][0], bf[nt][1]);
        }
        __syncthreads();
    }

    float* dst = (kh == 0) ? g_baseA : g_baseB;
    #pragma unroll
    for (int mt = 0; mt < 4; mt++) {
        #pragma unroll
        for (int nt = 0; nt < 4; nt++) {
            int col = ntb * 128 + wn + nt * 8 + (lane & 3) * 2;
            float bb0 = 0.f, bb1 = 0.f;
            if (kh == 0) {
                bb0 = __ldg(b_ih + col) + __ldg(b_hh + col);
                bb1 = __ldg(b_ih + col + 1) + __ldg(b_hh + col + 1);
            }
            int m0 = wm + mt * 16 + (lane >> 2);
            if (m0 < BQ) {
                float2 v0 = { acc[mt][nt][0] + bb0, acc[mt][nt][1] + bb1 };
                *(float2*)&dst[m0 * G4 + col] = v0;
            }
            int m1 = m0 + 8;
            if (m1 < BQ) {
                float2 v1 = { acc[mt][nt][2] + bb0, acc[mt][nt][3] + bb1 };
                *(float2*)&dst[m1 * G4 + col] = v1;
            }
        }
    }
}

// ------------------------------------------------------------------
// kernel: init = tv @ [Wo;Wh;Wc]^T + bias  (fp16 HMMA, M=32 pad 128, K=512)
// seg 0 (o) -> writes g_X16 cols 0..511 directly (fp16)
// ------------------------------------------------------------------
__device__ __forceinline__ void init_load_tile(
    int kt, int buf, int tid, int ntb, uint32_t sbase)
{
    const int k0 = kt * 32;
    const uint32_t abase = sbase + buf * MMA_SMEM_BUF;
    const uint32_t bbase = abase + 10240;
    #pragma unroll
    for (int i = 0; i < 2; i++) {
        int ch  = tid + i * 256;
        int row = ch >> 2, kc = ch & 3;
        cp_async16(abase + row * 80 + kc * 16,
                   g_tv16 + (size_t)row * HH + k0 + kc * 8);
        cp_async16(bbase + row * 80 + kc * 16,
                   g_W3h + (size_t)(ntb * 128 + row) * HH + k0 + kc * 8);
    }
    cp_commit();
}

__global__ void __launch_bounds__(256) k_init_mma(const float* __restrict__ bo,
                                                  const float* __restrict__ bh,
                                                  const float* __restrict__ bc)
{
    __shared__ __align__(16) unsigned char smem[2 * MMA_SMEM_BUF];
    const int tid  = threadIdx.x;
    const int lane = tid & 31;
    const int warp = tid >> 5;
    const int ntb  = blockIdx.x;     // 0..11

    const int wm = (warp >> 2) * 64;
    const int wn = (warp & 3) * 32;

    uint32_t sbase = (uint32_t)__cvta_generic_to_shared(smem);

    float acc[4][4][4];
    #pragma unroll
    for (int i = 0; i < 4; i++)
        #pragma unroll
        for (int jj = 0; jj < 4; jj++) {
            acc[i][jj][0] = 0.f; acc[i][jj][1] = 0.f;
            acc[i][jj][2] = 0.f; acc[i][jj][3] = 0.f;
        }

    const int amat  = lane >> 3;
    const uint32_t a_lane_off = (uint32_t)((wm + (amat & 1) * 8 + (lane & 7)) * 80
                                           + ((amat >> 1) * 8) * 2);
    const int blane = lane & 15;
    const uint32_t b_lane_off = (uint32_t)(10240 + (wn + (blane & 7)) * 80
                                           + ((blane >> 3) * 8) * 2);

    const int NKT = 16;
    init_load_tile(0, 0, tid, ntb, sbase);

    for (int kt = 0; kt < NKT; kt++) {
        if (kt + 1 < NKT) {
            init_load_tile(kt + 1, (kt + 1) & 1, tid, ntb, sbase);
            asm volatile("cp.async.wait_group 1;");
        } else {
            asm volatile("cp.async.wait_group 0;");
        }
        __syncthreads();

        const uint32_t abase = sbase + (kt & 1) * MMA_SMEM_BUF;
        #pragma unroll
        for (int k16 = 0; k16 < 2; k16++) {
            uint32_t af[4][4];
            uint32_t bf[4][2];
            #pragma unroll
            for (int mt = 0; mt < 4; mt++) {
                uint32_t ad = abase + a_lane_off + mt * (16 * 80) + k16 * 32;
                ldsm_x4(af[mt][0], af[mt][1], af[mt][2], af[mt][3], ad);
            }
            #pragma unroll
            for (int nt = 0; nt < 4; nt++) {
                uint32_t bd = abase + b_lane_off + nt * (8 * 80) + k16 * 32;
                ldsm_x2(bf[nt][0], bf[nt][1], bd);
            }
            #pragma unroll
            for (int mt = 0; mt < 4; mt++)
                #pragma unroll
                for (int nt = 0; nt < 4; nt++)
                    mma16816(acc[mt][nt][0], acc[mt][nt][1],
                             acc[mt][nt][2], acc[mt][nt][3],
                             af[mt][0], af[mt][1], af[mt][2], af[mt][3],
                             bf[nt][0], bf[nt][1]);
        }
        __syncthreads();
    }

    const int seg = ntb >> 2;                // 0=o, 1=h0, 2=c0
    const float* bias = (seg == 0) ? bo : (seg == 1) ? bh : bc;

    #pragma unroll
    for (int mt = 0; mt < 4; mt++) {
        #pragma unroll
        for (int nt = 0; nt < 4; nt++) {
            int cg = ntb * 128 + wn + nt * 8 + (lane & 3) * 2;
            int cs = cg & 511;
            float bb0 = __ldg(bias + cs);
            float bb1 = __ldg(bias + cs + 1);
            #pragma unroll
            for (int half2i = 0; half2i < 2; half2i++) {
                int m = wm + mt * 16 + (lane >> 2) + half2i * 8;
                if (m < BQ) {
                    float v0 = acc[mt][nt][half2i * 2 + 0] + bb0;
                    float v1 = acc[mt][nt][half2i * 2 + 1] + bb1;
                    if (seg == 0) {
                        *(__half2*)&g_X16[m * 1024 + cs] = __floats2half2_rn(v0, v1);
                    } else if (seg == 1) {
                        *(__half2*)&g_h16[m * HH + cs] = __floats2half2_rn(v0, v1);
                    } else {
                        float2 vv = { v0, v1 };
                        *(float2*)&g_c0[m * HH + cs] = vv;
                    }
                }
            }
        }
    }
}

// ------------------------------------------------------------------
// kernel: logits via fp16 HMMA, single pass (K = 512)
// ------------------------------------------------------------------
__device__ __forceinline__ void logits_load_tile(
    int kt, int buf, int tid, int mtb, int ntb, uint32_t sbase)
{
    const int k0 = kt * 32;
    const __half* A = g_h16 + BQ * HH;
    const uint32_t abase = sbase + buf * MMA_SMEM_BUF;
    const uint32_t bbase = abase + 10240;
    #pragma unroll
    for (int i = 0; i < 2; i++) {
        int ch  = tid + i * 256;
        int row = ch >> 2, kc = ch & 3;
        cp_async16(abase + row * 80 + kc * 16,
                   A + (size_t)(mtb * 128 + row) * HH + k0 + kc * 8);
        cp_async16(bbase + row * 80 + kc * 16,
                   g_Bh + (size_t)(ntb * 128 + row) * HH + k0 + kc * 8);
    }
    cp_commit();
}

__global__ void __launch_bounds__(256) k_logits_mma(const float* __restrict__ bv,
                                                    float* __restrict__ out)
{
    __shared__ __align__(16) unsigned char smem[2 * MMA_SMEM_BUF];
    const int tid  = threadIdx.x;
    const int lane = tid & 31;
    const int warp = tid >> 5;
    const int ntb  = blockIdx.x;     // 0..78
    const int mtb  = blockIdx.y;     // 0..31

    const int wm = (warp >> 2) * 64;
    const int wn = (warp & 3) * 32;

    uint32_t sbase = (uint32_t)__cvta_generic_to_shared(smem);

    float acc[4][4][4];
    #pragma unroll
    for (int i = 0; i < 4; i++)
        #pragma unroll
        for (int jj = 0; jj < 4; jj++) {
            acc[i][jj][0] = 0.f; acc[i][jj][1] = 0.f;
            acc[i][jj][2] = 0.f; acc[i][jj][3] = 0.f;
        }

    const int amat  = lane >> 3;
    const uint32_t a_lane_off = (uint32_t)((wm + (amat & 1) * 8 + (lane & 7)) * 80
                                           + ((amat >> 1) * 8) * 2);
    const int blane = lane & 15;
    const uint32_t b_lane_off = (uint32_t)(10240 + (wn + (blane & 7)) * 80
                                           + ((blane >> 3) * 8) * 2);

    const int NKT = 16;
    logits_load_tile(0, 0, tid, mtb, ntb, sbase);

    for (int kt = 0; kt < NKT; kt++) {
        if (kt + 1 < NKT) {
            logits_load_tile(kt + 1, (kt + 1) & 1, tid, mtb, ntb, sbase);
            asm volatile("cp.async.wait_group 1;");
        } else {
            asm volatile("cp.async.wait_group 0;");
        }
        __syncthreads();

        const uint32_t abase = sbase + (kt & 1) * MMA_SMEM_BUF;
        #pragma unroll
        for (int k16 = 0; k16 < 2; k16++) {
            uint32_t af[4][4];
            uint32_t bf[4][2];
            #pragma unroll
            for (int mt = 0; mt < 4; mt++) {
                uint32_t ad = abase + a_lane_off + mt * (16 * 80) + k16 * 32;
                ldsm_x4(af[mt][0], af[mt][1], af[mt][2], af[mt][3], ad);
            }
            #pragma unroll
            for (int nt = 0; nt < 4; nt++) {
                uint32_t bd = abase + b_lane_off + nt * (8 * 80) + k16 * 32;
                ldsm_x2(bf[nt][0], bf[nt][1], bd);
            }
            #pragma unroll
            for (int mt = 0; mt < 4; mt++)
                #pragma unroll
                for (int nt = 0; nt < 4; nt++)
                    mma16816(acc[mt][nt][0], acc[mt][nt][1],
                             acc[mt][nt][2], acc[mt][nt][3],
                             af[mt][0], af[mt][1], af[mt][2], af[mt][3],
                             bf[nt][0], bf[nt][1]);
        }
        __syncthreads();
    }

    #pragma unroll
    for (int mt = 0; mt < 4; mt++) {
        #pragma unroll
        for (int nt = 0; nt < 4; nt++) {
            int col = ntb * 128 + wn + nt * 8 + (lane & 3) * 2;
            if (col < VV) {
                float bb0 = __ldg(bv + col);
                float bb1 = __ldg(bv + col + 1);
                int m0 = mtb * 128 + wm + mt * 16 + (lane >> 2);
                int bI = m0 & 31, tI = m0 >> 5;
                float2 v0 = { acc[mt][nt][0] + bb0, acc[mt][nt][1] + bb1 };
                *(float2*)(out + (size_t)bI * TT * VV + (size_t)tI * VV + col) = v0;
                int m1 = m0 + 8;
                bI = m1 & 31; tI = m1 >> 5;
                float2 v1 = { acc[mt][nt][2] + bb0, acc[mt][nt][3] + bb1 };
                *(float2*)(out + (size_t)bI * TT * VV + (size_t)tI * VV + col) = v1;
            }
        }
    }
}

// ------------------------------------------------------------------
extern "C" void kernel_launch(void* const* d_in, const int* in_sizes, int n_in,
                              void* d_out, int out_size)
{
    const float* tv    = (const float*)d_in[0];
    const int*   texts = (const int*)  d_in[1];
    const int*   start = (const int*)  d_in[3];
    const float* emb   = (const float*)d_in[4];
    const float* W_ih  = (const float*)d_in[5];
    const float* b_ih  = (const float*)d_in[6];
    const float* W_hh  = (const float*)d_in[7];
    const float* b_hh  = (const float*)d_in[8];
    const float* Wo_w  = (const float*)d_in[9];
    const float* Wo_b  = (const float*)d_in[10];
    const float* Wh_w  = (const float*)d_in[11];
    const float* Wh_b  = (const float*)d_in[12];
    const float* Wc_w  = (const float*)d_in[13];
    const float* Wc_b  = (const float*)d_in[14];
    const float* Wv_w  = (const float*)d_in[15];
    const float* Wv_b  = (const float*)d_in[16];
    float* out = (float*)d_out;

    cudaFuncSetAttribute(k_lstm, cudaFuncAttributeMaxDynamicSharedMemorySize, LSTM_SMEM);

    k_convAll<<<10464, 256>>>(tv, Wo_w, Wh_w, Wc_w, W_ih, W_hh, Wv_w,
                              emb, texts, start);
    k_init_mma<<<12, 256>>>(Wo_b, Wh_b, Wc_b);
    k_base_mma<<<32, 256>>>(b_ih, b_hh);
    k_G_mma<<<dim3(G4 / 128, (TT * BQ) / 128), 256>>>();
    k_lstm<<<128, 128, LSTM_SMEM>>>();
    k_logits_mma<<<dim3(VPAD / 128, (TT * BQ) / 128), 256>>>(Wv_b, out);
}

// round 17
// speedup vs baseline: 1.0704x; 1.0704x over previous
#include <cuda_runtime.h>
#include <cuda_bf16.h>
#include <cuda_fp16.h>
#include <cstdint>
#include <math.h>

#define BQ   32
#define TT   128
#define EE   256
#define HH   512
#define ENCC 512
#define VV   10000
#define G4   2048          // 4*H
#define XW   1280          // E + H + ENC
#define VPAD 10112         // 79 * 128

// ------------------------------------------------------------------
// scratch (static device globals; no allocations allowed)
// ------------------------------------------------------------------
__device__ float g_c0[BQ * HH];
__device__ float g_baseA[BQ * G4];                // K half 0 (+ biases)
__device__ float g_baseB[BQ * G4];                // K half 1
__device__ unsigned g_bar_count;
__device__ unsigned g_bar_gen;

// fp16 operands
__device__ __half g_G16[TT * BQ * G4];            // per-step gate input (16 MB)
__device__ __half g_h16[(TT + 1) * BQ * HH];      // slot0=h0, slot t+1 = h after step t
__device__ __half g_Bh[VPAD * HH];                // logits B (Wv) fp16
__device__ __half g_E[TT * BQ * EE];              // gathered prev-token embeddings
__device__ __half g_Wih16[G4 * EE];               // W_ih[:, :E] fp16
__device__ __half g_Wihb[G4 * 1024];              // W_ih[:, E:] fp16
__device__ __half g_Whh16[G4 * HH];               // W_hh fp16
__device__ __half g_X16[128 * 1024];              // [o|tv] fp16, rows 32..127 zero
__device__ __half g_tv16[128 * HH];               // tv fp16, rows 32..127 zero
__device__ __half g_W3h[3 * HH * HH];             // [Wo;Wh;Wc] fp16

// ------------------------------------------------------------------
// merged conversion + gather kernel. chunk = 4 fp32 / 8 fp16 elems.
// cum ranges: 4096 8192 204800 335872 860160 1122304 2416640 2678784
// grid = 10464 x 256
// ------------------------------------------------------------------
__global__ void k_convAll(const float* __restrict__ tv,
                          const float* __restrict__ Wo,
                          const float* __restrict__ Wh,
                          const float* __restrict__ Wc,
                          const float* __restrict__ W_ih,
                          const float* __restrict__ W_hh,
                          const float* __restrict__ Wv,
                          const float* __restrict__ emb,
                          const int*   __restrict__ texts,
                          const int*   __restrict__ startp)
{
    int ci = blockIdx.x * 256 + threadIdx.x;
    if (ci < 4096) {
        int e = ci * 4;                              // 32*512 tv -> g_tv16
        float4 v = *(const float4*)(tv + e);
        *(__half2*)(g_tv16 + e)     = __floats2half2_rn(v.x, v.y);
        *(__half2*)(g_tv16 + e + 2) = __floats2half2_rn(v.z, v.w);
    } else if (ci < 8192) {
        int e = (ci - 4096) * 4;                     // tv -> X16 cols 512..1023
        int b = e >> 9, k = e & 511;
        float4 v = *(const float4*)(tv + b * ENCC + k);
        *(__half2*)(g_X16 + b * 1024 + 512 + k)     = __floats2half2_rn(v.x, v.y);
        *(__half2*)(g_X16 + b * 1024 + 512 + k + 2) = __floats2half2_rn(v.z, v.w);
    } else if (ci < 204800) {
        int e = (ci - 8192) * 4;
        int n = e >> 9, k = e & 511;
        const float* src = (n < 512) ? (Wo + n * 512 + k)
                         : (n < 1024) ? (Wh + (n - 512) * 512 + k)
                                      : (Wc + (n - 1024) * 512 + k);
        float4 v = *(const float4*)src;
        *(__half2*)(g_W3h + e)     = __floats2half2_rn(v.x, v.y);
        *(__half2*)(g_W3h + e + 2) = __floats2half2_rn(v.z, v.w);
    } else if (ci < 335872) {
        int e = (ci - 204800) * 4;
        int n = e >> 8, k = e & 255;
        float4 v = *(const float4*)(W_ih + (size_t)n * XW + k);
        *(__half2*)(g_Wih16 + (size_t)n * EE + k)     = __floats2half2_rn(v.x, v.y);
        *(__half2*)(g_Wih16 + (size_t)n * EE + k + 2) = __floats2half2_rn(v.z, v.w);
    } else if (ci < 860160) {
        int e = (ci - 335872) * 4;
        int n = e >> 10, k = e & 1023;
        float4 v = *(const float4*)(W_ih + (size_t)n * XW + EE + k);
        *(__half2*)(g_Wihb + (size_t)n * 1024 + k)     = __floats2half2_rn(v.x, v.y);
        *(__half2*)(g_Wihb + (size_t)n * 1024 + k + 2) = __floats2half2_rn(v.z, v.w);
    } else if (ci < 1122304) {
        int e = (ci - 860160) * 4;
        float4 v = *(const float4*)(W_hh + e);
        *(__half2*)(g_Whh16 + e)     = __floats2half2_rn(v.x, v.y);
        *(__half2*)(g_Whh16 + e + 2) = __floats2half2_rn(v.z, v.w);
    } else if (ci < 2416640) {
        size_t e = (size_t)(ci - 1122304) * 4;
        int n = (int)(e >> 9);
        if (n < VV) {
            float4 v = *(const float4*)(Wv + e);
            *(__half2*)(g_Bh + e)     = __floats2half2_rn(v.x, v.y);
            *(__half2*)(g_Bh + e + 2) = __floats2half2_rn(v.z, v.w);
        } else {
            *(__half2*)(g_Bh + e)     = __floats2half2_rn(0.f, 0.f);
            *(__half2*)(g_Bh + e + 2) = __floats2half2_rn(0.f, 0.f);
        }
    } else if (ci < 2678784) {
        int idx = ci - 2416640;                      // gather: 4096 rows x 64 chunks
        int r = idx >> 6, k = (idx & 63) * 4;
        int t = r >> 5, b = r & 31;
        int tok = (t == 0) ? startp[0] : texts[b * TT + t - 1];
        float4 v = *(const float4*)(emb + (size_t)tok * EE + k);
        *(__half2*)(g_E + (size_t)r * EE + k)     = __floats2half2_rn(v.x, v.y);
        *(__half2*)(g_E + (size_t)r * EE + k + 2) = __floats2half2_rn(v.z, v.w);
    }
}

// ------------------------------------------------------------------
// mma / ldmatrix / cp.async helpers
// ------------------------------------------------------------------
__device__ __forceinline__ void cp_async16(uint32_t dst, const void* src)
{
    asm volatile("cp.async.cg.shared.global [%0], [%1], 16;" :: "r"(dst), "l"(src));
}
__device__ __forceinline__ void cp_async8(uint32_t dst, const void* src)
{
    asm volatile("cp.async.ca.shared.global [%0], [%1], 8;" :: "r"(dst), "l"(src));
}
__device__ __forceinline__ void cp_commit()
{
    asm volatile("cp.async.commit_group;");
}
__device__ __forceinline__ void cp_wait_all()
{
    asm volatile("cp.async.wait_group 0;");
}
__device__ __forceinline__ void ldsm_x4(uint32_t& r0, uint32_t& r1,
                                        uint32_t& r2, uint32_t& r3, uint32_t addr)
{
    asm volatile("ldmatrix.sync.aligned.m8n8.x4.shared.b16 {%0,%1,%2,%3}, [%4];"
                 : "=r"(r0), "=r"(r1), "=r"(r2), "=r"(r3) : "r"(addr));
}
__device__ __forceinline__ void ldsm_x2(uint32_t& r0, uint32_t& r1, uint32_t addr)
{
    asm volatile("ldmatrix.sync.aligned.m8n8.x2.shared.b16 {%0,%1}, [%2];"
                 : "=r"(r0), "=r"(r1) : "r"(addr));
}
__device__ __forceinline__ void mma16816(float& c0, float& c1, float& c2, float& c3,
                                         uint32_t a0, uint32_t a1, uint32_t a2, uint32_t a3,
                                         uint32_t b0, uint32_t b1)
{
    asm volatile("mma.sync.aligned.m16n8k16.row.col.f32.f16.f16.f32 "
                 "{%0,%1,%2,%3}, {%4,%5,%6,%7}, {%8,%9}, {%0,%1,%2,%3};"
                 : "+f"(c0), "+f"(c1), "+f"(c2), "+f"(c3)
                 : "r"(a0), "r"(a1), "r"(a2), "r"(a3), "r"(b0), "r"(b1));
}

__device__ __forceinline__ float fsigm(float x)
{
    x = fminf(fmaxf(x, -30.f), 30.f);
    return __fdividef(1.f, 1.f + __expf(-x));
}
__device__ __forceinline__ float ftanh(float x)
{
    x = fminf(fmaxf(x, -15.f), 15.f);
    float e = __expf(2.f * x);
    return __fdividef(e - 1.f, e + 1.f);
}

// ------------------------------------------------------------------
// kernel: sequential LSTM via HMMA (persistent, 128 CTAs x 128 thr)
// R15-proven structure (flat barrier); barrier skipped on final step.
// SMEM: sW 16x1040 (16640) | sH 32x1040 (33280) | sG 2x1024
// ------------------------------------------------------------------
#define SW_OFF 0
#define SH_OFF 16640
#define SG_OFF 49920
#define LSTM_SMEM 51968

__global__ void __launch_bounds__(128, 1) k_lstm()
{
    extern __shared__ __align__(16) char smem[];
    uint32_t sbase = (uint32_t)__cvta_generic_to_shared(smem);
    __shared__ unsigned sGen;

    const int tid  = threadIdx.x;
    const int lane = tid & 31;
    const int w    = tid >> 5;          // warp 0..3
    const int p    = blockIdx.x;        // 0..127

    for (int i = 0; i < 8; i++) {
        int idx = tid + i * 128;
        int lr = idx >> 6, seg = idx & 63;
        int n  = (lr >> 2) * HH + p * 4 + (lr & 3);
        cp_async16(sbase + SW_OFF + lr * 1040 + seg * 16,
                   g_Whh16 + (size_t)n * HH + seg * 8);
    }
    cp_commit(); cp_wait_all();

    const int q    = lane >> 2;                 // valid for lane<16
    const int colb = w * 8 + (lane & 3) * 2;
    float cs0 = 0.f, cs1 = 0.f;
    if (lane < 16) {
        cs0 = g_c0[colb * HH + p * 4 + q];
        cs1 = g_c0[(colb + 1) * HH + p * 4 + q];
    }

    if (tid == 0) sGen = g_bar_gen;
    __syncthreads();
    const unsigned base_gen = sGen;

    const int amat = lane >> 3;
    const uint32_t aoff = sbase + SW_OFF
        + (uint32_t)(((amat & 1) * 8 + (lane & 7)) * 1040 + ((amat >> 1) * 8) * 2);
    const uint32_t boff = sbase + SH_OFF
        + (uint32_t)((w * 8 + (lane & 7)) * 1040 + (lane >> 3) * 16);

    const int gb_b = tid & 31, gb_g = tid >> 5;

    cp_async8(sbase + SG_OFF + (gb_g * 32 + gb_b) * 8,
              g_G16 + (size_t)gb_b * G4 + gb_g * HH + p * 4);
    cp_commit();

    for (int t = 0; t < TT; t++) {
        {
            const __half* hsrc = g_h16 + (size_t)t * (BQ * HH);
            #pragma unroll
            for (int j = 0; j < 16; j++) {
                int idx = lane + j * 32;
                int row = idx >> 6, seg = idx & 63;
                cp_async16(sbase + SH_OFF + (w * 8 + row) * 1040 + seg * 16,
                           hsrc + (size_t)(w * 8 + row) * HH + seg * 8);
            }
            cp_commit();
        }
        if (t + 1 < TT) {
            cp_async8(sbase + SG_OFF + ((t + 1) & 1) * 1024 + (gb_g * 32 + gb_b) * 8,
                      g_G16 + (size_t)((t + 1) * BQ + gb_b) * G4 + gb_g * HH + p * 4);
            cp_commit();
            asm volatile("cp.async.wait_group 1;");
        } else {
            asm volatile("cp.async.wait_group 0;");
        }
        __syncwarp();

        float acc[4][4];
        #pragma unroll
        for (int s = 0; s < 4; s++)
            { acc[s][0] = 0.f; acc[s][1] = 0.f; acc[s][2] = 0.f; acc[s][3] = 0.f; }

        #pragma unroll
        for (int i = 0; i < 16; i++) {
            uint32_t b0, b1, b2, b3;
            ldsm_x4(b0, b1, b2, b3, boff + i * 64);
            uint32_t a0, a1, a2, a3;
            ldsm_x4(a0, a1, a2, a3, aoff + (2 * i) * 32);
            int s0 = (2 * i) & 3;
            mma16816(acc[s0][0], acc[s0][1], acc[s0][2], acc[s0][3],
                     a0, a1, a2, a3, b0, b1);
            ldsm_x4(a0, a1, a2, a3, aoff + (2 * i + 1) * 32);
            int s1 = (2 * i + 1) & 3;
            mma16816(acc[s1][0], acc[s1][1], acc[s1][2], acc[s1][3],
                     a0, a1, a2, a3, b2, b3);
        }
        float g0 = (acc[0][0] + acc[1][0]) + (acc[2][0] + acc[3][0]);
        float g1 = (acc[0][1] + acc[1][1]) + (acc[2][1] + acc[3][1]);
        float g2 = (acc[0][2] + acc[1][2]) + (acc[2][2] + acc[3][2]);
        float g3 = (acc[0][3] + acc[1][3]) + (acc[2][3] + acc[3][3]);

        __syncthreads();

        const __half* sGc = (const __half*)(smem + SG_OFF + (t & 1) * 1024);
        {
            int r0 = lane >> 2;
            int gg = r0 >> 2, qq = r0 & 3;
            g0 += __half2float(sGc[(gg * 32 + colb) * 4 + qq]);
            g1 += __half2float(sGc[(gg * 32 + colb + 1) * 4 + qq]);
            g2 += __half2float(sGc[((gg + 2) * 32 + colb) * 4 + qq]);
            g3 += __half2float(sGc[((gg + 2) * 32 + colb + 1) * 4 + qq]);
        }

        float f0 = __shfl_xor_sync(0xffffffffu, g0, 16);
        float f1 = __shfl_xor_sync(0xffffffffu, g1, 16);
        float o0 = __shfl_xor_sync(0xffffffffu, g2, 16);
        float o1 = __shfl_xor_sync(0xffffffffu, g3, 16);

        if (lane < 16) {
            float i0 = fsigm(g0), i1 = fsigm(g1);
            float t0 = ftanh(g2), t1 = ftanh(g3);
            float F0 = fsigm(f0), F1 = fsigm(f1);
            float O0 = fsigm(o0), O1 = fsigm(o1);
            cs0 = F0 * cs0 + i0 * t0;
            cs1 = F1 * cs1 + i1 * t1;
            float h0 = O0 * ftanh(cs0);
            float h1 = O1 * ftanh(cs1);
            size_t hb = (size_t)(t + 1) * (BQ * HH) + p * 4 + q;
            g_h16[hb + (size_t)colb * HH]       = __float2half_rn(h0);
            g_h16[hb + (size_t)(colb + 1) * HH] = __float2half_rn(h1);
        }

        // ---- flat grid barrier (skipped after final step) ----
        if (t + 1 < TT) {
            __threadfence();
            __syncthreads();
            if (tid == 0) {
                unsigned target = base_gen + (unsigned)(t + 1);
                unsigned arr = atomicAdd(&g_bar_count, 1u);
                if (arr == 127u) {
                    g_bar_count = 0u;
                    __threadfence();
                    atomicExch(&g_bar_gen, target);
                } else {
                    volatile unsigned* vg = &g_bar_gen;
                    while (*vg < target) { }
                }
                __threadfence();
            }
            __syncthreads();
        }
    }
    // restore gen invariant for next graph replay (all CTAs observed release
    // of step TT-1... last step has no release; bump gen so base_gen stays
    // consistent across replays)
    __syncthreads();
    if (tid == 0 && p == 0) {
        atomicExch(&g_bar_gen, base_gen + (unsigned)(TT - 1));
    }
}

#define MMA_SMEM_BUF 20480           // A(10240) + B(10240) per buffer

// ------------------------------------------------------------------
// kernel: G = E @ Wih^T + baseA + baseB  (fp16 HMMA, K=256) -> g_G16
// ------------------------------------------------------------------
__device__ __forceinline__ void g_load_tile(
    int kt, int buf, int tid, int mtb, int ntb, uint32_t sbase)
{
    const int k0 = kt * 32;
    const uint32_t abase = sbase + buf * MMA_SMEM_BUF;
    const uint32_t bbase = abase + 10240;
    #pragma unroll
    for (int i = 0; i < 2; i++) {
        int ch  = tid + i * 256;
        int row = ch >> 2, kc = ch & 3;
        cp_async16(abase + row * 80 + kc * 16,
                   g_E + (size_t)(mtb * 128 + row) * EE + k0 + kc * 8);
        cp_async16(bbase + row * 80 + kc * 16,
                   g_Wih16 + (size_t)(ntb * 128 + row) * EE + k0 + kc * 8);
    }
    cp_commit();
}

__global__ void __launch_bounds__(256) k_G_mma()
{
    __shared__ __align__(16) unsigned char smem[2 * MMA_SMEM_BUF];
    const int tid  = threadIdx.x;
    const int lane = tid & 31;
    const int warp = tid >> 5;
    const int ntb  = blockIdx.x;     // 0..15
    const int mtb  = blockIdx.y;     // 0..31

    const int wm = (warp >> 2) * 64;
    const int wn = (warp & 3) * 32;

    uint32_t sbase = (uint32_t)__cvta_generic_to_shared(smem);

    float acc[4][4][4];
    #pragma unroll
    for (int i = 0; i < 4; i++)
        #pragma unroll
        for (int jj = 0; jj < 4; jj++) {
            acc[i][jj][0] = 0.f; acc[i][jj][1] = 0.f;
            acc[i][jj][2] = 0.f; acc[i][jj][3] = 0.f;
        }

    const int amat  = lane >> 3;
    const uint32_t a_lane_off = (uint32_t)((wm + (amat & 1) * 8 + (lane & 7)) * 80
                                           + ((amat >> 1) * 8) * 2);
    const int blane = lane & 15;
    const uint32_t b_lane_off = (uint32_t)(10240 + (wn + (blane & 7)) * 80
                                           + ((blane >> 3) * 8) * 2);

    const int NKT = 8;
    g_load_tile(0, 0, tid, mtb, ntb, sbase);

    for (int kt = 0; kt < NKT; kt++) {
        if (kt + 1 < NKT) {
            g_load_tile(kt + 1, (kt + 1) & 1, tid, mtb, ntb, sbase);
            asm volatile("cp.async.wait_group 1;");
        } else {
            asm volatile("cp.async.wait_group 0;");
        }
        __syncthreads();

        const uint32_t abase = sbase + (kt & 1) * MMA_SMEM_BUF;
        #pragma unroll
        for (int k16 = 0; k16 < 2; k16++) {
            uint32_t af[4][4];
            uint32_t bf[4][2];
            #pragma unroll
            for (int mt = 0; mt < 4; mt++) {
                uint32_t ad = abase + a_lane_off + mt * (16 * 80) + k16 * 32;
                ldsm_x4(af[mt][0], af[mt][1], af[mt][2], af[mt][3], ad);
            }
            #pragma unroll
            for (int nt = 0; nt < 4; nt++) {
                uint32_t bd = abase + b_lane_off + nt * (8 * 80) + k16 * 32;
                ldsm_x2(bf[nt][0], bf[nt][1], bd);
            }
            #pragma unroll
            for (int mt = 0; mt < 4; mt++)
                #pragma unroll
                for (int nt = 0; nt < 4; nt++)
                    mma16816(acc[mt][nt][0], acc[mt][nt][1],
                             acc[mt][nt][2], acc[mt][nt][3],
                             af[mt][0], af[mt][1], af[mt][2], af[mt][3],
                             bf[nt][0], bf[nt][1]);
        }
        __syncthreads();
    }

    #pragma unroll
    for (int mt = 0; mt < 4; mt++) {
        #pragma unroll
        for (int nt = 0; nt < 4; nt++) {
            int col = ntb * 128 + wn + nt * 8 + (lane & 3) * 2;
            int m0 = mtb * 128 + wm + mt * 16 + (lane >> 2);
            float2 ba0 = *(const float2*)&g_baseA[(m0 & 31) * G4 + col];
            float2 bb0 = *(const float2*)&g_baseB[(m0 & 31) * G4 + col];
            *(__half2*)&g_G16[(size_t)m0 * G4 + col] =
                __floats2half2_rn(acc[mt][nt][0] + ba0.x + bb0.x,
                                  acc[mt][nt][1] + ba0.y + bb0.y);
            int m1 = m0 + 8;
            float2 ba1 = *(const float2*)&g_baseA[(m1 & 31) * G4 + col];
            float2 bb1 = *(const float2*)&g_baseB[(m1 & 31) * G4 + col];
            *(__half2*)&g_G16[(size_t)m1 * G4 + col] =
                __floats2half2_rn(acc[mt][nt][2] + ba1.x + bb1.x,
                                  acc[mt][nt][3] + ba1.y + bb1.y);
        }
    }
}

// ------------------------------------------------------------------
// kernel: base = X @ Wihb^T + biases, split-K x2 (fp16 HMMA, K=512 each)
// ------------------------------------------------------------------
__device__ __forceinline__ void base_load_tile(
    int kt, int buf, int tid, int ntb, int kbase, uint32_t sbase)
{
    const int k0 = kbase + kt * 32;
    const uint32_t abase = sbase + buf * MMA_SMEM_BUF;
    const uint32_t bbase = abase + 10240;
    #pragma unroll
    for (int i = 0; i < 2; i++) {
        int ch  = tid + i * 256;
        int row = ch >> 2, kc = ch & 3;
        cp_async16(abase + row * 80 + kc * 16,
                   g_X16 + (size_t)row * 1024 + k0 + kc * 8);
        cp_async16(bbase + row * 80 + kc * 16,
                   g_Wihb + (size_t)(ntb * 128 + row) * 1024 + k0 + kc * 8);
    }
    cp_commit();
}

__global__ void __launch_bounds__(256) k_base_mma(const float* __restrict__ b_ih,
                                                  const float* __restrict__ b_hh)
{
    __shared__ __align__(16) unsigned char smem[2 * MMA_SMEM_BUF];
    const int tid  = threadIdx.x;
    const int lane = tid & 31;
    const int warp = tid >> 5;
    const int ntb  = blockIdx.x & 15;
    const int kh   = blockIdx.x >> 4;      // 0 or 1
    const int kbase = kh * 512;

    const int wm = (warp >> 2) * 64;
    const int wn = (warp & 3) * 32;

    uint32_t sbase = (uint32_t)__cvta_generic_to_shared(smem);

    float acc[4][4][4];
    #pragma unroll
    for (int i = 0; i < 4; i++)
        #pragma unroll
        for (int jj = 0; jj < 4; jj++) {
            acc[i][jj][0] = 0.f; acc[i][jj][1] = 0.f;
            acc[i][jj][2] = 0.f; acc[i][jj][3] = 0.f;
        }

    const int amat  = lane >> 3;
    const uint32_t a_lane_off = (uint32_t)((wm + (amat & 1) * 8 + (lane & 7)) * 80
                                           + ((amat >> 1) * 8) * 2);
    const int blane = lane & 15;
    const uint32_t b_lane_off = (uint32_t)(10240 + (wn + (blane & 7)) * 80
                                           + ((blane >> 3) * 8) * 2);

    const int NKT = 16;                    // 512 / 32
    base_load_tile(0, 0, tid, ntb, kbase, sbase);

    for (int kt = 0; kt < NKT; kt++) {
        if (kt + 1 < NKT) {
            base_load_tile(kt + 1, (kt + 1) & 1, tid, ntb, kbase, sbase);
            asm volatile("cp.async.wait_group 1;");
        } else {
            asm volatile("cp.async.wait_group 0;");
        }
        __syncthreads();

        const uint32_t abase = sbase + (kt & 1) * MMA_SMEM_BUF;
        #pragma unroll
        for (int k16 = 0; k16 < 2; k16++) {
            uint32_t af[4][4];
            uint32_t bf[4][2];
            #pragma unroll
            for (int mt = 0; mt < 4; mt++) {
                uint32_t ad = abase + a_lane_off + mt * (16 * 80) + k16 * 32;
                ldsm_x4(af[mt][0], af[mt][1], af[mt][2], af[mt][3], ad);
            }
            #pragma unroll
            for (int nt = 0; nt < 4; nt++) {
                uint32_t bd = abase + b_lane_off + nt * (8 * 80) + k16 * 32;
                ldsm_x2(bf[nt][0], bf[nt][1], bd);
            }
            #pragma unroll
            for (int mt = 0; mt < 4; mt++)
                #pragma unroll
                for (int nt = 0; nt < 4; nt++)
                    mma16816(acc[mt][nt][0], acc[mt][nt][1],
                             acc[mt][nt][2], acc[mt][nt][3],
                             af[mt][0], af[mt][1], af[mt][2], af[mt][3],
                             bf[nt][0], bf[nt][1]);
        }
        __syncthreads();
    }

    float* dst = (kh == 0) ? g_baseA : g_baseB;
    #pragma unroll
    for (int mt = 0; mt < 4; mt++) {
        #pragma unroll
        for (int nt = 0; nt < 4; nt++) {
            int col = ntb * 128 + wn + nt * 8 + (lane & 3) * 2;
            float bb0 = 0.f, bb1 = 0.f;
            if (kh == 0) {
                bb0 = __ldg(b_ih + col) + __ldg(b_hh + col);
                bb1 = __ldg(b_ih + col + 1) + __ldg(b_hh + col + 1);
            }
            int m0 = wm + mt * 16 + (lane >> 2);
            if (m0 < BQ) {
                float2 v0 = { acc[mt][nt][0] + bb0, acc[mt][nt][1] + bb1 };
                *(float2*)&dst[m0 * G4 + col] = v0;
            }
            int m1 = m0 + 8;
            if (m1 < BQ) {
                float2 v1 = { acc[mt][nt][2] + bb0, acc[mt][nt][3] + bb1 };
                *(float2*)&dst[m1 * G4 + col] = v1;
            }
        }
    }
}

// ------------------------------------------------------------------
// kernel: init = tv @ [Wo;Wh;Wc]^T + bias  (fp16 HMMA, M=32 pad 128, K=512)
// seg 0 (o) -> writes g_X16 cols 0..511 directly (fp16)
// ------------------------------------------------------------------
__device__ __forceinline__ void init_load_tile(
    int kt, int buf, int tid, int ntb, uint32_t sbase)
{
    const int k0 = kt * 32;
    const uint32_t abase = sbase + buf * MMA_SMEM_BUF;
    const uint32_t bbase = abase + 10240;
    #pragma unroll
    for (int i = 0; i < 2; i++) {
        int ch  = tid + i * 256;
        int row = ch >> 2, kc = ch & 3;
        cp_async16(abase + row * 80 + kc * 16,
                   g_tv16 + (size_t)row * HH + k0 + kc * 8);
        cp_async16(bbase + row * 80 + kc * 16,
                   g_W3h + (size_t)(ntb * 128 + row) * HH + k0 + kc * 8);
    }
    cp_commit();
}

__global__ void __launch_bounds__(256) k_init_mma(const float* __restrict__ bo,
                                                  const float* __restrict__ bh,
                                                  const float* __restrict__ bc)
{
    __shared__ __align__(16) unsigned char smem[2 * MMA_SMEM_BUF];
    const int tid  = threadIdx.x;
    const int lane = tid & 31;
    const int warp = tid >> 5;
    const int ntb  = blockIdx.x;     // 0..11

    const int wm = (warp >> 2) * 64;
    const int wn = (warp & 3) * 32;

    uint32_t sbase = (uint32_t)__cvta_generic_to_shared(smem);

    float acc[4][4][4];
    #pragma unroll
    for (int i = 0; i < 4; i++)
        #pragma unroll
        for (int jj = 0; jj < 4; jj++) {
            acc[i][jj][0] = 0.f; acc[i][jj][1] = 0.f;
            acc[i][jj][2] = 0.f; acc[i][jj][3] = 0.f;
        }

    const int amat  = lane >> 3;
    const uint32_t a_lane_off = (uint32_t)((wm + (amat & 1) * 8 + (lane & 7)) * 80
                                           + ((amat >> 1) * 8) * 2);
    const int blane = lane & 15;
    const uint32_t b_lane_off = (uint32_t)(10240 + (wn + (blane & 7)) * 80
                                           + ((blane >> 3) * 8) * 2);

    const int NKT = 16;
    init_load_tile(0, 0, tid, ntb, sbase);

    for (int kt = 0; kt < NKT; kt++) {
        if (kt + 1 < NKT) {
            init_load_tile(kt + 1, (kt + 1) & 1, tid, ntb, sbase);
            asm volatile("cp.async.wait_group 1;");
        } else {
            asm volatile("cp.async.wait_group 0;");
        }
        __syncthreads();

        const uint32_t abase = sbase + (kt & 1) * MMA_SMEM_BUF;
        #pragma unroll
        for (int k16 = 0; k16 < 2; k16++) {
            uint32_t af[4][4];
            uint32_t bf[4][2];
            #pragma unroll
            for (int mt = 0; mt < 4; mt++) {
                uint32_t ad = abase + a_lane_off + mt * (16 * 80) + k16 * 32;
                ldsm_x4(af[mt][0], af[mt][1], af[mt][2], af[mt][3], ad);
            }
            #pragma unroll
            for (int nt = 0; nt < 4; nt++) {
                uint32_t bd = abase + b_lane_off + nt * (8 * 80) + k16 * 32;
                ldsm_x2(bf[nt][0], bf[nt][1], bd);
            }
            #pragma unroll
            for (int mt = 0; mt < 4; mt++)
                #pragma unroll
                for (int nt = 0; nt < 4; nt++)
                    mma16816(acc[mt][nt][0], acc[mt][nt][1],
                             acc[mt][nt][2], acc[mt][nt][3],
                             af[mt][0], af[mt][1], af[mt][2], af[mt][3],
                             bf[nt][0], bf[nt][1]);
        }
        __syncthreads();
    }

    const int seg = ntb >> 2;                // 0=o, 1=h0, 2=c0
    const float* bias = (seg == 0) ? bo : (seg == 1) ? bh : bc;

    #pragma unroll
    for (int mt = 0; mt < 4; mt++) {
        #pragma unroll
        for (int nt = 0; nt < 4; nt++) {
            int cg = ntb * 128 + wn + nt * 8 + (lane & 3) * 2;
            int cs = cg & 511;
            float bb0 = __ldg(bias + cs);
            float bb1 = __ldg(bias + cs + 1);
            #pragma unroll
            for (int half2i = 0; half2i < 2; half2i++) {
                int m = wm + mt * 16 + (lane >> 2) + half2i * 8;
                if (m < BQ) {
                    float v0 = acc[mt][nt][half2i * 2 + 0] + bb0;
                    float v1 = acc[mt][nt][half2i * 2 + 1] + bb1;
                    if (seg == 0) {
                        *(__half2*)&g_X16[m * 1024 + cs] = __floats2half2_rn(v0, v1);
                    } else if (seg == 1) {
                        *(__half2*)&g_h16[m * HH + cs] = __floats2half2_rn(v0, v1);
                    } else {
                        float2 vv = { v0, v1 };
                        *(float2*)&g_c0[m * HH + cs] = vv;
                    }
                }
            }
        }
    }
}

// ------------------------------------------------------------------
// kernel: logits via fp16 HMMA, single pass (K = 512)
// ------------------------------------------------------------------
__device__ __forceinline__ void logits_load_tile(
    int kt, int buf, int tid, int mtb, int ntb, uint32_t sbase)
{
    const int k0 = kt * 32;
    const __half* A = g_h16 + BQ * HH;
    const uint32_t abase = sbase + buf * MMA_SMEM_BUF;
    const uint32_t bbase = abase + 10240;
    #pragma unroll
    for (int i = 0; i < 2; i++) {
        int ch  = tid + i * 256;
        int row = ch >> 2, kc = ch & 3;
        cp_async16(abase + row * 80 + kc * 16,
                   A + (size_t)(mtb * 128 + row) * HH + k0 + kc * 8);
        cp_async16(bbase + row * 80 + kc * 16,
                   g_Bh + (size_t)(ntb * 128 + row) * HH + k0 + kc * 8);
    }
    cp_commit();
}

__global__ void __launch_bounds__(256) k_logits_mma(const float* __restrict__ bv,
                                                    float* __restrict__ out)
{
    __shared__ __align__(16) unsigned char smem[2 * MMA_SMEM_BUF];
    const int tid  = threadIdx.x;
    const int lane = tid & 31;
    const int warp = tid >> 5;
    const int ntb  = blockIdx.x;     // 0..78
    const int mtb  = blockIdx.y;     // 0..31

    const int wm = (warp >> 2) * 64;
    const int wn = (warp & 3) * 32;

    uint32_t sbase = (uint32_t)__cvta_generic_to_shared(smem);

    float acc[4][4][4];
    #pragma unroll
    for (int i = 0; i < 4; i++)
        #pragma unroll
        for (int jj = 0; jj < 4; jj++) {
            acc[i][jj][0] = 0.f; acc[i][jj][1] = 0.f;
            acc[i][jj][2] = 0.f; acc[i][jj][3] = 0.f;
        }

    const int amat  = lane >> 3;
    const uint32_t a_lane_off = (uint32_t)((wm + (amat & 1) * 8 + (lane & 7)) * 80
                                           + ((amat >> 1) * 8) * 2);
    const int blane = lane & 15;
    const uint32_t b_lane_off = (uint32_t)(10240 + (wn + (blane & 7)) * 80
                                           + ((blane >> 3) * 8) * 2);

    const int NKT = 16;
    logits_load_tile(0, 0, tid, mtb, ntb, sbase);

    for (int kt = 0; kt < NKT; kt++) {
        if (kt + 1 < NKT) {
            logits_load_tile(kt + 1, (kt + 1) & 1, tid, mtb, ntb, sbase);
            asm volatile("cp.async.wait_group 1;");
        } else {
            asm volatile("cp.async.wait_group 0;");
        }
        __syncthreads();

        const uint32_t abase = sbase + (kt & 1) * MMA_SMEM_BUF;
        #pragma unroll
        for (int k16 = 0; k16 < 2; k16++) {
            uint32_t af[4][4];
            uint32_t bf[4][2];
            #pragma unroll
            for (int mt = 0; mt < 4; mt++) {
                uint32_t ad = abase + a_lane_off + mt * (16 * 80) + k16 * 32;
                ldsm_x4(af[mt][0], af[mt][1], af[mt][2], af[mt][3], ad);
            }
            #pragma unroll
            for (int nt = 0; nt < 4; nt++) {
                uint32_t bd = abase + b_lane_off + nt * (8 * 80) + k16 * 32;
                ldsm_x2(bf[nt][0], bf[nt][1], bd);
            }
            #pragma unroll
            for (int mt = 0; mt < 4; mt++)
                #pragma unroll
                for (int nt = 0; nt < 4; nt++)
                    mma16816(acc[mt][nt][0], acc[mt][nt][1],
                             acc[mt][nt][2], acc[mt][nt][3],
                             af[mt][0], af[mt][1], af[mt][2], af[mt][3],
                             bf[nt][0], bf[nt][1]);
        }
        __syncthreads();
    }

    #pragma unroll
    for (int mt = 0; mt < 4; mt++) {
        #pragma unroll
        for (int nt = 0; nt < 4; nt++) {
            int col = ntb * 128 + wn + nt * 8 + (lane & 3) * 2;
            if (col < VV) {
                float bb0 = __ldg(bv + col);
                float bb1 = __ldg(bv + col + 1);
                int m0 = mtb * 128 + wm + mt * 16 + (lane >> 2);
                int bI = m0 & 31, tI = m0 >> 5;
                float2 v0 = { acc[mt][nt][0] + bb0, acc[mt][nt][1] + bb1 };
                *(float2*)(out + (size_t)bI * TT * VV + (size_t)tI * VV + col) = v0;
                int m1 = m0 + 8;
                bI = m1 & 31; tI = m1 >> 5;
                float2 v1 = { acc[mt][nt][2] + bb0, acc[mt][nt][3] + bb1 };
                *(float2*)(out + (size_t)bI * TT * VV + (size_t)tI * VV + col) = v1;
            }
        }
    }
}

// ------------------------------------------------------------------
extern "C" void kernel_launch(void* const* d_in, const int* in_sizes, int n_in,
                              void* d_out, int out_size)
{
    const float* tv    = (const float*)d_in[0];
    const int*   texts = (const int*)  d_in[1];
    const int*   start = (const int*)  d_in[3];
    const float* emb   = (const float*)d_in[4];
    const float* W_ih  = (const float*)d_in[5];
    const float* b_ih  = (const float*)d_in[6];
    const float* W_hh  = (const float*)d_in[7];
    const float* b_hh  = (const float*)d_in[8];
    const float* Wo_w  = (const float*)d_in[9];
    const float* Wo_b  = (const float*)d_in[10];
    const float* Wh_w  = (const float*)d_in[11];
    const float* Wh_b  = (const float*)d_in[12];
    const float* Wc_w  = (const float*)d_in[13];
    const float* Wc_b  = (const float*)d_in[14];
    const float* Wv_w  = (const float*)d_in[15];
    const float* Wv_b  = (const float*)d_in[16];
    float* out = (float*)d_out;

    cudaFuncSetAttribute(k_lstm, cudaFuncAttributeMaxDynamicSharedMemorySize, LSTM_SMEM);

    k_convAll<<<10464, 256>>>(tv, Wo_w, Wh_w, Wc_w, W_ih, W_hh, Wv_w,
                              emb, texts, start);
    k_init_mma<<<12, 256>>>(Wo_b, Wh_b, Wc_b);
    k_base_mma<<<32, 256>>>(b_ih, b_hh);
    k_G_mma<<<dim3(G4 / 128, (TT * BQ) / 128), 256>>>();
    k_lstm<<<128, 128, LSTM_SMEM>>>();
    k_logits_mma<<<dim3(VPAD / 128, (TT * BQ) / 128), 256>>>(Wv_b, out);
}